// round 6
// baseline (speedup 1.0000x reference)
#include <cuda_runtime.h>
#include <cuda_bf16.h>

#define N_NODES   8192
#define K         32
#define CUTOFF2   100.0f
#define CAND      64           // max candidates per node (graph size <= ~60 w.h.p.)
#define WPB       2            // warps per block

__global__ __launch_bounds__(WPB * 32)
void radius_graph_kernel(const float* __restrict__ pos,
                         const int* __restrict__ batch,
                         float* __restrict__ out) {
    __shared__ unsigned long long s_key[WPB][CAND];   // (d2 bits << 32) | idx, 16B-aligned

    const int w    = threadIdx.x >> 5;
    const int lane = threadIdx.x & 31;
    const int i    = blockIdx.x * WPB + w;

    unsigned long long* __restrict__ keyw = s_key[w];

    const int g = batch[i];

    // ---- fused bidirectional segment scan: both directions' loads in flight ----
    int seg_lo = -1, seg_hi = -1;
    for (int base = 0; seg_lo < 0 || seg_hi < 0; base += 32) {
        const int jl = i - 1 - base - lane;
        const int jh = i + 1 + base + lane;
        const bool offl = (jl < 0)        || (batch[jl] != g);
        const bool offh = (jh >= N_NODES) || (batch[jh] != g);
        const unsigned ml = __ballot_sync(0xffffffffu, offl);
        const unsigned mh = __ballot_sync(0xffffffffu, offh);
        if (seg_lo < 0 && ml) seg_lo = i - base - (__ffs(ml) - 1);
        if (seg_hi < 0 && mh) seg_hi = i + 1 + base + (__ffs(mh) - 1);
    }

    const float xi = pos[3 * i + 0];
    const float yi = pos[3 * i + 1];
    const float zi = pos[3 * i + 2];
    // sq exactly as jnp.sum(pos*pos, -1): (x*x + y*y) + z*z, no FMA contraction
    const float sqi = __fadd_rn(__fadd_rn(__fmul_rn(xi, xi), __fmul_rn(yi, yi)),
                                __fmul_rn(zi, zi));

    // ---- gather valid candidates via ballot-prefix append (no atomics) ----
    int cnt = 0;                                            // lane-uniform
    for (int jb = seg_lo; jb < seg_hi && cnt < CAND; jb += 32) {
        const int j = jb + lane;
        bool valid = (j < seg_hi) && (j != i);
        float d2 = 0.0f;
        if (valid) {
            const float xj = pos[3 * j + 0];
            const float yj = pos[3 * j + 1];
            const float zj = pos[3 * j + 2];
            const float sqj = __fadd_rn(__fadd_rn(__fmul_rn(xj, xj), __fmul_rn(yj, yj)),
                                        __fmul_rn(zj, zj));
            const float dot = __fadd_rn(__fadd_rn(__fmul_rn(xi, xj), __fmul_rn(yi, yj)),
                                        __fmul_rn(zi, zj));
            d2 = __fsub_rn(__fadd_rn(sqi, sqj), __fmul_rn(2.0f, dot));
            d2 = fmaxf(d2, 0.0f);
            valid = (d2 <= CUTOFF2);
        }
        const unsigned m = __ballot_sync(0xffffffffu, valid);
        if (valid) {
            const int pos_c = cnt + __popc(m & ((1u << lane) - 1u));
            if (pos_c < CAND) {
                keyw[pos_c] = ((unsigned long long)__float_as_uint(d2) << 32)
                              | (unsigned)j;
            }
        }
        cnt += __popc(m);
    }
    __syncwarp();
    const int C = cnt < CAND ? cnt : CAND;

    const int NK = N_NODES * K;
    float* __restrict__ out_row = out;
    float* __restrict__ out_col = out + NK;
    float* __restrict__ out_w   = out + 2 * NK;
    float* __restrict__ out_m   = out + 3 * NK;
    const int base = i * K;

    // row is always i; padded slots (rank >= min(C,K)) get col=i, w=0, m=0
    out_row[base + lane] = (float)i;
    const int Cc = C < K ? C : K;
    if (lane >= Cc) {
        out_col[base + lane] = (float)i;
        out_w  [base + lane] = 0.0f;
        out_m  [base + lane] = 0.0f;
    }

    // ---- rank candidates by 64-bit key (d2 asc, idx asc); write top-K slots ----
    const ulonglong2* __restrict__ key2 = (const ulonglong2*)keyw;
    const int half = C >> 1;
    for (int c = lane; c < C; c += 32) {
        const unsigned long long kc = keyw[c];
        int rank = 0;
        #pragma unroll 4
        for (int h = 0; h < half; h++) {
            const ulonglong2 k2 = key2[h];                 // LDS.128, broadcast
            rank += (int)(k2.x < kc) + (int)(k2.y < kc);
        }
        if (C & 1) rank += (int)(keyw[C - 1] < kc);
        if (rank < K) {
            const float d2c = __uint_as_float((unsigned)(kc >> 32));
            const int   jc  = (int)(unsigned)(kc & 0xffffffffu);
            out_col[base + rank] = (float)jc;
            out_w  [base + rank] = sqrtf(d2c);
            out_m  [base + rank] = 1.0f;
        }
    }
}

extern "C" void kernel_launch(void* const* d_in, const int* in_sizes, int n_in,
                              void* d_out, int out_size) {
    const float* pos   = (const float*)d_in[0];
    const int*   batch = (const int*)d_in[1];
    float*       out   = (float*)d_out;

    const int blocks = N_NODES / WPB;   // 4096
    radius_graph_kernel<<<blocks, WPB * 32>>>(pos, batch, out);
}

// round 7
// speedup vs baseline: 1.0208x; 1.0208x over previous
#include <cuda_runtime.h>
#include <cuda_bf16.h>

#define N_NODES   8192
#define K         32
#define CUTOFF2   100.0f
#define CAND      96           // buffer per node; observed max segment ~55
#define WPB       2            // warps per block; each warp handles 2 adjacent nodes

__global__ __launch_bounds__(WPB * 32)
void radius_graph_kernel(const float* __restrict__ pos,
                         const int* __restrict__ batch,
                         float* __restrict__ out) {
    __shared__ unsigned long long s_key[WPB][2][CAND + 2];  // (d2 bits << 32) | idx

    const int w    = threadIdx.x >> 5;
    const int lane = threadIdx.x & 31;
    const int i0   = (blockIdx.x * WPB + w) * 2;
    const int i1   = i0 + 1;

    const int g0 = batch[i0];
    const int g1 = batch[i1];
    const bool same = (g0 == g1);

    // ---- one bidirectional scan serves both nodes ----
    // lo scan backward from i0 (graph g0), hi scan forward from i1 (graph g1)
    int lo0 = -1, hi1 = -1;
    for (int base = 0; lo0 < 0 || hi1 < 0; base += 32) {
        const int jl = i0 - 1 - base - lane;
        const int jh = i1 + 1 + base + lane;
        const bool offl = (jl < 0)        || (batch[jl] != g0);
        const bool offh = (jh >= N_NODES) || (batch[jh] != g1);
        const unsigned ml = __ballot_sync(0xffffffffu, offl);
        const unsigned mh = __ballot_sync(0xffffffffu, offh);
        if (lo0 < 0 && ml) lo0 = i0 - base - (__ffs(ml) - 1);
        if (hi1 < 0 && mh) hi1 = i1 + 1 + base + (__ffs(mh) - 1);
    }
    // adjacent + sorted: if graphs differ, the boundary is exactly at i1
    const int hi0 = same ? hi1 : i1;
    const int lo1 = same ? lo0 : i1;

    const float x0 = pos[3 * i0 + 0], y0 = pos[3 * i0 + 1], z0 = pos[3 * i0 + 2];
    const float x1 = pos[3 * i1 + 0], y1 = pos[3 * i1 + 1], z1 = pos[3 * i1 + 2];
    // sq exactly as jnp.sum(pos*pos, -1): (x*x + y*y) + z*z, no FMA contraction
    const float sq0 = __fadd_rn(__fadd_rn(__fmul_rn(x0, x0), __fmul_rn(y0, y0)),
                                __fmul_rn(z0, z0));
    const float sq1 = __fadd_rn(__fadd_rn(__fmul_rn(x1, x1), __fmul_rn(y1, y1)),
                                __fmul_rn(z1, z1));

    unsigned long long* __restrict__ key0 = s_key[w][0];
    unsigned long long* __restrict__ key1 = s_key[w][1];

    // ---- gather for both nodes over the union range; pos[j] loaded once ----
    int cnt0 = 0, cnt1 = 0;
    for (int jb = lo0; jb < hi1; jb += 32) {
        const int j = jb + lane;
        const bool in = (j < hi1);
        float xj = 0.f, yj = 0.f, zj = 0.f;
        if (in) { xj = pos[3 * j + 0]; yj = pos[3 * j + 1]; zj = pos[3 * j + 2]; }
        const float sqj = __fadd_rn(__fadd_rn(__fmul_rn(xj, xj), __fmul_rn(yj, yj)),
                                    __fmul_rn(zj, zj));

        const float dot0 = __fadd_rn(__fadd_rn(__fmul_rn(x0, xj), __fmul_rn(y0, yj)),
                                     __fmul_rn(z0, zj));
        float d20 = __fsub_rn(__fadd_rn(sq0, sqj), __fmul_rn(2.0f, dot0));
        d20 = fmaxf(d20, 0.0f);
        const bool v0 = in && (j < hi0) && (j != i0) && (d20 <= CUTOFF2);

        const float dot1 = __fadd_rn(__fadd_rn(__fmul_rn(x1, xj), __fmul_rn(y1, yj)),
                                     __fmul_rn(z1, zj));
        float d21 = __fsub_rn(__fadd_rn(sq1, sqj), __fmul_rn(2.0f, dot1));
        d21 = fmaxf(d21, 0.0f);
        const bool v1 = in && (j >= lo1) && (j != i1) && (d21 <= CUTOFF2);

        const unsigned m0 = __ballot_sync(0xffffffffu, v0);
        const unsigned m1 = __ballot_sync(0xffffffffu, v1);
        if (v0) {
            const int p = cnt0 + __popc(m0 & ((1u << lane) - 1u));
            key0[p] = ((unsigned long long)__float_as_uint(d20) << 32) | (unsigned)j;
        }
        if (v1) {
            const int p = cnt1 + __popc(m1 & ((1u << lane) - 1u));
            key1[p] = ((unsigned long long)__float_as_uint(d21) << 32) | (unsigned)j;
        }
        cnt0 += __popc(m0);
        cnt1 += __popc(m1);
    }
    // sentinel pad to even length (rank loop runs even trips, no tail branch)
    if (lane < 2) {
        key0[cnt0 + lane] = ~0ull;
        key1[cnt1 + lane] = ~0ull;
    }
    __syncwarp();

    const int NK = N_NODES * K;
    float* __restrict__ out_row = out;
    float* __restrict__ out_col = out + NK;
    float* __restrict__ out_w   = out + 2 * NK;
    float* __restrict__ out_m   = out + 3 * NK;

    #pragma unroll
    for (int n = 0; n < 2; n++) {
        const int i = n ? i1 : i0;
        const int C = n ? cnt1 : cnt0;
        const unsigned long long* __restrict__ keyw = n ? key1 : key0;
        const int base = i * K;

        // row is always i; padded slots (rank >= min(C,K)) get col=i, w=0, m=0
        out_row[base + lane] = (float)i;
        const int Cc = C < K ? C : K;
        if (lane >= Cc) {
            out_col[base + lane] = (float)i;
            out_w  [base + lane] = 0.0f;
            out_m  [base + lane] = 0.0f;
        }

        // ---- rank candidates by 64-bit key (d2 asc, idx asc) ----
        const ulonglong2* __restrict__ key2 = (const ulonglong2*)keyw;
        const int halves = (C + 1) >> 1;                   // sentinels absorb odd tail
        for (int c = lane; c < C; c += 32) {
            const unsigned long long kc = keyw[c];
            int rank = 0;
            #pragma unroll 4
            for (int h = 0; h < halves; h++) {
                const ulonglong2 k2 = key2[h];             // LDS.128, broadcast
                rank += (int)(k2.x < kc) + (int)(k2.y < kc);
            }
            if (rank < K) {
                const float d2c = __uint_as_float((unsigned)(kc >> 32));
                const int   jc  = (int)(unsigned)(kc & 0xffffffffu);
                out_col[base + rank] = (float)jc;
                out_w  [base + rank] = sqrtf(d2c);
                out_m  [base + rank] = 1.0f;
            }
        }
    }
}

extern "C" void kernel_launch(void* const* d_in, const int* in_sizes, int n_in,
                              void* d_out, int out_size) {
    const float* pos   = (const float*)d_in[0];
    const int*   batch = (const int*)d_in[1];
    float*       out   = (float*)d_out;

    const int blocks = N_NODES / (2 * WPB);   // 2048
    radius_graph_kernel<<<blocks, WPB * 32>>>(pos, batch, out);
}